// round 14
// baseline (speedup 1.0000x reference)
#include <cuda_runtime.h>
#include <math.h>
#include <float.h>

#define NOBJ   16
#define P      4096
#define EPSF   1e-12f
#define GRID   64
#define NBINS  (GRID * GRID)          // 4096
#define GMIN   (-5.0f)
#define GEXT   10.0f
#define CELLF  (GEXT / (float)GRID)   // 0.15625
#define CELL2  (CELLF * CELLF)
#define INVC   ((float)GRID / GEXT)   // 6.4
#define NSLOT  32                     // 2 sets x 16 objects
#define CSTRIDE (NBINS + 4)           // 16B-aligned slot stride
#define NQ     (2 * NOBJ * P)         // 131072 queries
#define TB     1024                   // build threads

// Sorted points and cell offsets per (set, object) slot.
__device__ __align__(16) float2       g_pts[NSLOT * P];
__device__ __align__(16) unsigned int g_cstart[NSLOT * CSTRIDE];
__device__ float        g_mask[NOBJ];

// Tail (phase-2) work list
__device__ unsigned int g_tail_count;
__device__ int          g_tail_qid [NQ];
__device__ float        g_tail_best[NQ];

__device__ __forceinline__ int cell_of(float v) {
    int c = (int)((v - GMIN) * INVC);
    return min(GRID - 1, max(0, c));
}

// ---------------------------------------------------------------------------
// Kernel 1: build — counting-sort each (set, obj) into the 64x64 grid.
// One CTA of 1024 threads per slot. Single-pass hierarchical scan (3 barriers).
// Also computes g_mask (set2), zeroes output + tail count.
// ---------------------------------------------------------------------------
__global__ void __launch_bounds__(TB)
build_kernel(const float* __restrict__ set1, const float* __restrict__ set2,
             float* __restrict__ out)
{
    const int slot = blockIdx.x;
    const int set  = slot >> 4;
    const int obj  = slot & 15;
    const float2* pts = (const float2*)((set == 0 ? set1 : set2) + (size_t)obj * P * 2);

    __shared__ __align__(16) unsigned int hist[NBINS];   // 16 KB
    __shared__ unsigned int wsum[32];
    __shared__ float mred[32];

    const int tid  = threadIdx.x;
    const int lane = tid & 31, warp = tid >> 5;

    // zero histogram (4 bins/thread via uint4)
    ((uint4*)hist)[tid] = make_uint4(0u, 0u, 0u, 0u);
    __syncthreads();

    // histogram pass (4 points/thread) + mask sum
    float msum = 0.f;
    #pragma unroll
    for (int v = 0; v < P / TB; v++) {
        const int i = v * TB + tid;
        float2 p = pts[i];
        msum += p.x + p.y;
        int c = cell_of(p.y) * GRID + cell_of(p.x);
        atomicAdd(&hist[c], 1u);
    }

    if (set == 1) {
        #pragma unroll
        for (int o = 16; o; o >>= 1) msum += __shfl_xor_sync(0xFFFFFFFFu, msum, o);
        if (lane == 0) mred[warp] = msum;
    }
    if (slot == 0 && tid == 0) { *out = 0.f; g_tail_count = 0; }
    __syncthreads();

    if (set == 1 && tid == 0) {
        float t = 0.f;
        #pragma unroll
        for (int w = 0; w < 32; w++) t += mred[w];
        g_mask[obj] = (t >= 0.f) ? 1.f : 0.f;
    }

    // ---- single-pass exclusive scan over 4096 bins ----
    // each thread owns 4 consecutive bins
    uint4 v4 = ((uint4*)hist)[tid];
    const unsigned int tsum = v4.x + v4.y + v4.z + v4.w;

    // warp inclusive scan of per-thread sums
    unsigned int incl = tsum;
    #pragma unroll
    for (int o = 1; o < 32; o <<= 1) {
        unsigned int n = __shfl_up_sync(0xFFFFFFFFu, incl, o);
        if (lane >= o) incl += n;
    }
    if (lane == 31) wsum[warp] = incl;
    __syncthreads();

    // warp 0 scans the 32 warp totals (exclusive)
    if (warp == 0) {
        unsigned int w = wsum[lane];
        unsigned int wi = w;
        #pragma unroll
        for (int o = 1; o < 32; o <<= 1) {
            unsigned int n = __shfl_up_sync(0xFFFFFFFFu, wi, o);
            if (lane >= o) wi += n;
        }
        wsum[lane] = wi - w;
    }
    __syncthreads();

    const unsigned int base = (incl - tsum) + wsum[warp];
    uint4 o4;
    o4.x = base;
    o4.y = base + v4.x;
    o4.z = base + v4.x + v4.y;
    o4.w = base + v4.x + v4.y + v4.z;
    ((uint4*)hist)[tid] = o4;

    // persist starts (one uint4 per thread)
    unsigned int* cs = g_cstart + (size_t)slot * CSTRIDE;
    ((uint4*)cs)[tid] = o4;
    if (tid == 0) { cs[NBINS] = P; cs[NBINS + 1] = P; cs[NBINS + 2] = P; cs[NBINS + 3] = P; }
    __syncthreads();

    // scatter (hist becomes per-cell cursor), 4 points/thread
    float2* dst = g_pts + (size_t)slot * P;
    #pragma unroll
    for (int v = 0; v < P / TB; v++) {
        const int i = v * TB + tid;
        float2 p = pts[i];
        int c = cell_of(p.y) * GRID + cell_of(p.x);
        unsigned int pos = atomicAdd(&hist[c], 1u);
        dst[pos] = p;
    }
}

// ---------------------------------------------------------------------------
// Kernel 2 (phase 1): 3x3-only NN. If best <= CELL^2 the NN is proven found
// (unvisited cells are >= 1 cell away, clamped-query geometry). Otherwise
// push (qid, best) to the tail list. Target structure staged in smem.
// ---------------------------------------------------------------------------
__global__ void __launch_bounds__(256)
query_kernel(float* __restrict__ out)
{
    const int b     = blockIdx.x;
    const int chunk = b & 15;
    const int obj   = (b >> 4) & 15;
    const int dir   = b >> 8;

    const int qslot = (dir == 0) ? obj      : 16 + obj;
    const int tslot = (dir == 0) ? 16 + obj : obj;

    __shared__ __align__(16) float2       s_pts[P];           // 32 KB
    __shared__ __align__(16) unsigned int s_cs[NBINS + 1];    // 16 KB

    {
        const float4* src = (const float4*)(g_pts + (size_t)tslot * P);
        float4* dst = (float4*)s_pts;
        for (int i = threadIdx.x; i < P / 2; i += 256) dst[i] = src[i];
        const uint4* csrc = (const uint4*)(g_cstart + (size_t)tslot * CSTRIDE);
        uint4* cdst = (uint4*)s_cs;
        for (int i = threadIdx.x; i < NBINS / 4; i += 256) cdst[i] = csrc[i];
        if (threadIdx.x == 0) s_cs[NBINS] = P;
    }
    __syncthreads();

    const int qi  = chunk * 256 + threadIdx.x;
    const int qid = (dir * NOBJ + obj) * P + qi;
    const float2 qp = g_pts[(size_t)qslot * P + qi];
    const float qx = qp.x, qy = qp.y;
    const int cx = cell_of(qx), cy = cell_of(qy);

    float best = FLT_MAX;
    {
        const int j0 = max(cy - 1, 0), j1 = min(cy + 1, GRID - 1);
        const int i0 = max(cx - 1, 0), i1 = min(cx + 1, GRID - 1);
        for (int j = j0; j <= j1; j++) {
            const unsigned int k0 = s_cs[j * GRID + i0];
            const unsigned int k1 = s_cs[j * GRID + i1 + 1];
            for (unsigned int k = k0; k < k1; k++) {
                const float2 p = s_pts[k];
                const float dx = qx - p.x;
                const float dy = qy - p.y;
                best = fminf(best, fmaf(dx, dx, dy * dy));
            }
        }
    }

    const bool fail = (best > CELL2);
    float acc = fail ? 0.f : sqrtf(fmaxf(best, EPSF)) * g_mask[obj];

    // warp-aggregated tail push
    const unsigned int m = __ballot_sync(0xFFFFFFFFu, fail);
    if (m) {
        const int lane = threadIdx.x & 31;
        const int leader = __ffs(m) - 1;
        unsigned int base = 0;
        if (lane == leader) base = atomicAdd(&g_tail_count, (unsigned)__popc(m));
        base = __shfl_sync(0xFFFFFFFFu, base, leader);
        if (fail) {
            const int off = base + __popc(m & ((1u << lane) - 1u));
            g_tail_qid[off]  = qid;
            g_tail_best[off] = best;
        }
    }

    // block reduce + atomic
    #pragma unroll
    for (int o = 16; o; o >>= 1) acc += __shfl_xor_sync(0xFFFFFFFFu, acc, o);
    __shared__ float red[8];
    if ((threadIdx.x & 31) == 0) red[threadIdx.x >> 5] = acc;
    __syncthreads();
    if (threadIdx.x == 0) {
        float tot = 0.f;
        #pragma unroll
        for (int w = 0; w < 8; w++) tot += red[w];
        if (tot != 0.f)
            atomicAdd(out, tot * (0.5f / ((float)NOBJ * (float)P)));
    }
}

// ---------------------------------------------------------------------------
// Kernel 3 (phase 2): tail queries, one WARP per query. Lanes split box rows;
// box radius doubles 2,4,...,64; exact stop best <= (r*CELL)^2.
// ---------------------------------------------------------------------------
__global__ void __launch_bounds__(256)
tail_kernel(float* __restrict__ out)
{
    const int warps_per_cta = 256 / 32;
    const int gwarp = blockIdx.x * warps_per_cta + (threadIdx.x >> 5);
    const int nwarp = gridDim.x * warps_per_cta;
    const int lane  = threadIdx.x & 31;

    const unsigned int count = g_tail_count;
    float acc = 0.f;

    for (unsigned int t = gwarp; t < count; t += nwarp) {
        const int qid = g_tail_qid[t];
        float best    = g_tail_best[t];
        const int dir = qid >> 16;              // qid = (dir*16+obj)*4096 + qi
        const int obj = (qid >> 12) & 15;
        const int qi  = qid & (P - 1);

        const int qslot = (dir == 0) ? obj      : 16 + obj;
        const int tslot = (dir == 0) ? 16 + obj : obj;

        const float2 qp = g_pts[(size_t)qslot * P + qi];
        const float qx = qp.x, qy = qp.y;
        const unsigned int* __restrict__ cs = g_cstart + (size_t)tslot * CSTRIDE;
        const float2* __restrict__ tp = g_pts + (size_t)tslot * P;

        const int cx = cell_of(qx), cy = cell_of(qy);

        for (int r = 2; r <= GRID; r <<= 1) {
            const int y0 = max(cy - r, 0), y1 = min(cy + r, GRID - 1);
            const int x0 = max(cx - r, 0), x1 = min(cx + r, GRID - 1);

            float lb = FLT_MAX;
            for (int j = y0 + lane; j <= y1; j += 32) {
                const unsigned int k0 = __ldg(&cs[j * GRID + x0]);
                const unsigned int k1 = __ldg(&cs[j * GRID + x1 + 1]);
                for (unsigned int k = k0; k < k1; k++) {
                    const float2 p = __ldg(&tp[k]);
                    const float dx = qx - p.x;
                    const float dy = qy - p.y;
                    lb = fminf(lb, fmaf(dx, dx, dy * dy));
                }
            }
            #pragma unroll
            for (int o = 16; o; o >>= 1)
                lb = fminf(lb, __shfl_xor_sync(0xFFFFFFFFu, lb, o));
            best = fminf(best, lb);

            const bool full = (x0 == 0) && (y0 == 0) && (x1 == GRID - 1) && (y1 == GRID - 1);
            const float rb = (float)r * CELLF;
            if (best <= rb * rb || full) break;
        }

        acc += sqrtf(fmaxf(best, EPSF)) * g_mask[obj];   // identical on all lanes
    }

    if (lane == 0 && acc != 0.f)
        atomicAdd(out, acc * (0.5f / ((float)NOBJ * (float)P)));
}

// ---------------------------------------------------------------------------
extern "C" void kernel_launch(void* const* d_in, const int* in_sizes, int n_in,
                              void* d_out, int out_size)
{
    const float* set1 = (const float*)d_in[0];
    const float* set2 = (const float*)d_in[1];
    float* out = (float*)d_out;

    build_kernel<<<NSLOT, TB>>>(set1, set2, out);
    query_kernel<<<512, 256>>>(out);
    tail_kernel<<<148, 256>>>(out);
}

// round 15
// speedup vs baseline: 1.4287x; 1.4287x over previous
#include <cuda_runtime.h>
#include <math.h>
#include <float.h>

#define NOBJ   16
#define P      4096
#define EPSF   1e-12f
#define GRID   64
#define NBINS  (GRID * GRID)          // 4096
#define GMIN   (-5.0f)
#define GEXT   10.0f
#define CELLF  (GEXT / (float)GRID)   // 0.15625
#define CELL2  (CELLF * CELLF)
#define CELL2_2 (4.f * CELLF * CELLF) // (2*CELL)^2 : 5x5 exact-stop bound
#define INVC   ((float)GRID / GEXT)   // 6.4
#define NSLOT  32                     // 2 sets x 16 objects
#define CSTRIDE (NBINS + 4)           // 16B-aligned slot stride
#define NQ     (2 * NOBJ * P)         // 131072 queries
#define TB     1024                   // build threads

// Sorted points and cell offsets per (set, object) slot.
__device__ __align__(16) float2       g_pts[NSLOT * P];
__device__ __align__(16) unsigned int g_cstart[NSLOT * CSTRIDE];
__device__ float        g_mask[NOBJ];

// Tail (phase-2) work list
__device__ unsigned int g_tail_count;
__device__ int          g_tail_qid [NQ];
__device__ float        g_tail_best[NQ];

__device__ __forceinline__ int cell_of(float v) {
    int c = (int)((v - GMIN) * INVC);
    return min(GRID - 1, max(0, c));
}

// ---------------------------------------------------------------------------
// Kernel 1: build — counting-sort each (set, obj) into the 64x64 grid.
// One CTA of 1024 threads per slot; single-pass hierarchical scan.
// ---------------------------------------------------------------------------
__global__ void __launch_bounds__(TB)
build_kernel(const float* __restrict__ set1, const float* __restrict__ set2,
             float* __restrict__ out)
{
    const int slot = blockIdx.x;
    const int set  = slot >> 4;
    const int obj  = slot & 15;
    const float2* pts = (const float2*)((set == 0 ? set1 : set2) + (size_t)obj * P * 2);

    __shared__ __align__(16) unsigned int hist[NBINS];   // 16 KB
    __shared__ unsigned int wsum[32];
    __shared__ float mred[32];

    const int tid  = threadIdx.x;
    const int lane = tid & 31, warp = tid >> 5;

    ((uint4*)hist)[tid] = make_uint4(0u, 0u, 0u, 0u);
    __syncthreads();

    // histogram (4 points/thread) + mask sum
    float msum = 0.f;
    #pragma unroll
    for (int v = 0; v < P / TB; v++) {
        const int i = v * TB + tid;
        float2 p = pts[i];
        msum += p.x + p.y;
        int c = cell_of(p.y) * GRID + cell_of(p.x);
        atomicAdd(&hist[c], 1u);
    }

    if (set == 1) {
        #pragma unroll
        for (int o = 16; o; o >>= 1) msum += __shfl_xor_sync(0xFFFFFFFFu, msum, o);
        if (lane == 0) mred[warp] = msum;
    }
    if (slot == 0 && tid == 0) { *out = 0.f; g_tail_count = 0; }
    __syncthreads();

    if (set == 1 && tid == 0) {
        float t = 0.f;
        #pragma unroll
        for (int w = 0; w < 32; w++) t += mred[w];
        g_mask[obj] = (t >= 0.f) ? 1.f : 0.f;
    }

    // single-pass exclusive scan over 4096 bins (4 bins/thread)
    uint4 v4 = ((uint4*)hist)[tid];
    const unsigned int tsum = v4.x + v4.y + v4.z + v4.w;

    unsigned int incl = tsum;
    #pragma unroll
    for (int o = 1; o < 32; o <<= 1) {
        unsigned int n = __shfl_up_sync(0xFFFFFFFFu, incl, o);
        if (lane >= o) incl += n;
    }
    if (lane == 31) wsum[warp] = incl;
    __syncthreads();

    if (warp == 0) {
        unsigned int w = wsum[lane];
        unsigned int wi = w;
        #pragma unroll
        for (int o = 1; o < 32; o <<= 1) {
            unsigned int n = __shfl_up_sync(0xFFFFFFFFu, wi, o);
            if (lane >= o) wi += n;
        }
        wsum[lane] = wi - w;
    }
    __syncthreads();

    const unsigned int base = (incl - tsum) + wsum[warp];
    uint4 o4;
    o4.x = base;
    o4.y = base + v4.x;
    o4.z = base + v4.x + v4.y;
    o4.w = base + v4.x + v4.y + v4.z;
    ((uint4*)hist)[tid] = o4;

    unsigned int* cs = g_cstart + (size_t)slot * CSTRIDE;
    ((uint4*)cs)[tid] = o4;
    if (tid == 0) { cs[NBINS] = P; cs[NBINS + 1] = P; cs[NBINS + 2] = P; cs[NBINS + 3] = P; }
    __syncthreads();

    // scatter
    float2* dst = g_pts + (size_t)slot * P;
    #pragma unroll
    for (int v = 0; v < P / TB; v++) {
        const int i = v * TB + tid;
        float2 p = pts[i];
        int c = cell_of(p.y) * GRID + cell_of(p.x);
        unsigned int pos = atomicAdd(&hist[c], 1u);
        dst[pos] = p;
    }
}

// ---------------------------------------------------------------------------
// Kernel 2 (phase 1): 3x3 NN, escalate failures to 5x5 (still in smem).
// Exact-stop: best <= CELL^2 after 3x3, or best <= (2*CELL)^2 after 5x5
// (unvisited cells are >= 1 resp. 2 cells away; clamped-query geometry).
// Residual failures go to the tail list with r starting at 4.
// ---------------------------------------------------------------------------
__global__ void __launch_bounds__(256)
query_kernel(float* __restrict__ out)
{
    const int b     = blockIdx.x;
    const int chunk = b & 15;
    const int obj   = (b >> 4) & 15;
    const int dir   = b >> 8;

    const int qslot = (dir == 0) ? obj      : 16 + obj;
    const int tslot = (dir == 0) ? 16 + obj : obj;

    __shared__ __align__(16) float2       s_pts[P];           // 32 KB
    __shared__ __align__(16) unsigned int s_cs[NBINS + 1];    // 16 KB

    {
        const float4* src = (const float4*)(g_pts + (size_t)tslot * P);
        float4* dst = (float4*)s_pts;
        for (int i = threadIdx.x; i < P / 2; i += 256) dst[i] = src[i];
        const uint4* csrc = (const uint4*)(g_cstart + (size_t)tslot * CSTRIDE);
        uint4* cdst = (uint4*)s_cs;
        for (int i = threadIdx.x; i < NBINS / 4; i += 256) cdst[i] = csrc[i];
        if (threadIdx.x == 0) s_cs[NBINS] = P;
    }
    __syncthreads();

    const int qi  = chunk * 256 + threadIdx.x;
    const int qid = (dir * NOBJ + obj) * P + qi;
    const float2 qp = g_pts[(size_t)qslot * P + qi];
    const float qx = qp.x, qy = qp.y;
    const int cx = cell_of(qx), cy = cell_of(qy);

    float best = FLT_MAX;
    {
        const int j0 = max(cy - 1, 0), j1 = min(cy + 1, GRID - 1);
        const int i0 = max(cx - 1, 0), i1 = min(cx + 1, GRID - 1);
        for (int j = j0; j <= j1; j++) {
            const unsigned int k0 = s_cs[j * GRID + i0];
            const unsigned int k1 = s_cs[j * GRID + i1 + 1];
            for (unsigned int k = k0; k < k1; k++) {
                const float2 p = s_pts[k];
                const float dx = qx - p.x;
                const float dy = qy - p.y;
                best = fminf(best, fmaf(dx, dx, dy * dy));
            }
        }
    }

    // escalate to 5x5 ring (the 16 border cells of the 5x5 box) if needed
    if (best > CELL2) {
        const int j0 = max(cy - 2, 0), j1 = min(cy + 2, GRID - 1);
        const int i0 = max(cx - 2, 0), i1 = min(cx + 2, GRID - 1);
        for (int j = j0; j <= j1; j++) {
            const bool edge_row = (j == cy - 2) || (j == cy + 2);
            // edge rows: full span; middle rows: only the two border cells
            int ia = i0, ib = i1;
            if (!edge_row) {
                // left border cell
                if (cx - 2 >= 0) {
                    const int c = j * GRID + (cx - 2);
                    const unsigned int k0 = s_cs[c], k1 = s_cs[c + 1];
                    for (unsigned int k = k0; k < k1; k++) {
                        const float2 p = s_pts[k];
                        const float dx = qx - p.x;
                        const float dy = qy - p.y;
                        best = fminf(best, fmaf(dx, dx, dy * dy));
                    }
                }
                if (cx + 2 <= GRID - 1) {
                    const int c = j * GRID + (cx + 2);
                    const unsigned int k0 = s_cs[c], k1 = s_cs[c + 1];
                    for (unsigned int k = k0; k < k1; k++) {
                        const float2 p = s_pts[k];
                        const float dx = qx - p.x;
                        const float dy = qy - p.y;
                        best = fminf(best, fmaf(dx, dx, dy * dy));
                    }
                }
                continue;
            }
            const unsigned int k0 = s_cs[j * GRID + ia];
            const unsigned int k1 = s_cs[j * GRID + ib + 1];
            for (unsigned int k = k0; k < k1; k++) {
                const float2 p = s_pts[k];
                const float dx = qx - p.x;
                const float dy = qy - p.y;
                best = fminf(best, fmaf(dx, dx, dy * dy));
            }
        }
    }

    const bool fail = (best > CELL2_2);
    float acc = fail ? 0.f : sqrtf(fmaxf(best, EPSF)) * g_mask[obj];

    // warp-aggregated tail push
    const unsigned int m = __ballot_sync(0xFFFFFFFFu, fail);
    if (m) {
        const int lane = threadIdx.x & 31;
        const int leader = __ffs(m) - 1;
        unsigned int base = 0;
        if (lane == leader) base = atomicAdd(&g_tail_count, (unsigned)__popc(m));
        base = __shfl_sync(0xFFFFFFFFu, base, leader);
        if (fail) {
            const int off = base + __popc(m & ((1u << lane) - 1u));
            g_tail_qid[off]  = qid;
            g_tail_best[off] = best;
        }
    }

    // block reduce + atomic
    #pragma unroll
    for (int o = 16; o; o >>= 1) acc += __shfl_xor_sync(0xFFFFFFFFu, acc, o);
    __shared__ float red[8];
    if ((threadIdx.x & 31) == 0) red[threadIdx.x >> 5] = acc;
    __syncthreads();
    if (threadIdx.x == 0) {
        float tot = 0.f;
        #pragma unroll
        for (int w = 0; w < 8; w++) tot += red[w];
        if (tot != 0.f)
            atomicAdd(out, tot * (0.5f / ((float)NOBJ * (float)P)));
    }
}

// ---------------------------------------------------------------------------
// Kernel 3 (phase 2): residual tail queries, one WARP per query.
// Box radius doubles 4,8,...,64; exact stop best <= (r*CELL)^2.
// ---------------------------------------------------------------------------
__global__ void __launch_bounds__(128)
tail_kernel(float* __restrict__ out)
{
    const int warps_per_cta = 128 / 32;
    const int gwarp = blockIdx.x * warps_per_cta + (threadIdx.x >> 5);
    const int nwarp = gridDim.x * warps_per_cta;
    const int lane  = threadIdx.x & 31;

    const unsigned int count = g_tail_count;
    float acc = 0.f;

    for (unsigned int t = gwarp; t < count; t += nwarp) {
        const int qid = g_tail_qid[t];
        float best    = g_tail_best[t];
        const int dir = qid >> 16;
        const int obj = (qid >> 12) & 15;
        const int qi  = qid & (P - 1);

        const int qslot = (dir == 0) ? obj      : 16 + obj;
        const int tslot = (dir == 0) ? 16 + obj : obj;

        const float2 qp = g_pts[(size_t)qslot * P + qi];
        const float qx = qp.x, qy = qp.y;
        const unsigned int* __restrict__ cs = g_cstart + (size_t)tslot * CSTRIDE;
        const float2* __restrict__ tp = g_pts + (size_t)tslot * P;

        const int cx = cell_of(qx), cy = cell_of(qy);

        for (int r = 4; r <= GRID; r <<= 1) {
            const int y0 = max(cy - r, 0), y1 = min(cy + r, GRID - 1);
            const int x0 = max(cx - r, 0), x1 = min(cx + r, GRID - 1);

            float lb = FLT_MAX;
            for (int j = y0 + lane; j <= y1; j += 32) {
                const unsigned int k0 = __ldg(&cs[j * GRID + x0]);
                const unsigned int k1 = __ldg(&cs[j * GRID + x1 + 1]);
                for (unsigned int k = k0; k < k1; k++) {
                    const float2 p = __ldg(&tp[k]);
                    const float dx = qx - p.x;
                    const float dy = qy - p.y;
                    lb = fminf(lb, fmaf(dx, dx, dy * dy));
                }
            }
            #pragma unroll
            for (int o = 16; o; o >>= 1)
                lb = fminf(lb, __shfl_xor_sync(0xFFFFFFFFu, lb, o));
            best = fminf(best, lb);

            const bool full = (x0 == 0) && (y0 == 0) && (x1 == GRID - 1) && (y1 == GRID - 1);
            const float rb = (float)r * CELLF;
            if (best <= rb * rb || full) break;
        }

        acc += sqrtf(fmaxf(best, EPSF)) * g_mask[obj];   // identical on all lanes
    }

    if (lane == 0 && acc != 0.f)
        atomicAdd(out, acc * (0.5f / ((float)NOBJ * (float)P)));
}

// ---------------------------------------------------------------------------
extern "C" void kernel_launch(void* const* d_in, const int* in_sizes, int n_in,
                              void* d_out, int out_size)
{
    const float* set1 = (const float*)d_in[0];
    const float* set2 = (const float*)d_in[1];
    float* out = (float*)d_out;

    build_kernel<<<NSLOT, TB>>>(set1, set2, out);
    query_kernel<<<512, 256>>>(out);
    tail_kernel<<<148, 128>>>(out);
}

// round 16
// speedup vs baseline: 1.5568x; 1.0896x over previous
#include <cuda_runtime.h>
#include <math.h>
#include <float.h>

#define NOBJ   16
#define P      4096
#define EPSF   1e-12f
#define GRID   64
#define NBINS  (GRID * GRID)          // 4096
#define GMIN   (-5.0f)
#define GEXT   10.0f
#define CELLF  (GEXT / (float)GRID)   // 0.15625
#define CELL2  (CELLF * CELLF)
#define CELL2_2 (4.f * CELLF * CELLF) // (2*CELL)^2 : 5x5 exact-stop bound
#define INVC   ((float)GRID / GEXT)   // 6.4
#define NSLOT  32                     // 2 sets x 16 objects
#define CSTRIDE (NBINS + 4)           // 16B-aligned slot stride
#define NQ     (2 * NOBJ * P)         // 131072 queries
#define TB     1024                   // build threads

// Sorted points and cell offsets per (set, object) slot.
__device__ __align__(16) float2       g_pts[NSLOT * P];
__device__ __align__(16) unsigned int g_cstart[NSLOT * CSTRIDE];
__device__ float        g_mask[NOBJ];

// Tail (phase-2) work list
__device__ unsigned int g_tail_count;
__device__ int          g_tail_qid [NQ];
__device__ float        g_tail_best[NQ];

__device__ __forceinline__ int cell_of(float v) {
    int c = (int)((v - GMIN) * INVC);
    return min(GRID - 1, max(0, c));
}

// ---------------------------------------------------------------------------
// Kernel 1: build — counting-sort each (set, obj) into the 64x64 grid.
// Batched contiguous loads (2x float4 / thread) for MLP; scatter goes to a
// smem sorted buffer, then flushes to gmem coalesced.
// ---------------------------------------------------------------------------
__global__ void __launch_bounds__(TB)
build_kernel(const float* __restrict__ set1, const float* __restrict__ set2,
             float* __restrict__ out)
{
    const int slot = blockIdx.x;
    const int set  = slot >> 4;
    const int obj  = slot & 15;
    const float4* p4 = (const float4*)((set == 0 ? set1 : set2) + (size_t)obj * P * 2);

    __shared__ __align__(16) unsigned int hist[NBINS];     // 16 KB
    __shared__ __align__(16) float2       s_sorted[P];     // 32 KB
    __shared__ unsigned int wsum[32];
    __shared__ float mred[32];

    const int tid  = threadIdx.x;
    const int lane = tid & 31, warp = tid >> 5;

    ((uint4*)hist)[tid] = make_uint4(0u, 0u, 0u, 0u);
    __syncthreads();

    // batched load: thread t owns points 4t..4t+3 (two float4s)
    const float4 a = p4[2 * tid];
    const float4 b = p4[2 * tid + 1];
    const int c0 = cell_of(a.y) * GRID + cell_of(a.x);
    const int c1 = cell_of(a.w) * GRID + cell_of(a.z);
    const int c2 = cell_of(b.y) * GRID + cell_of(b.x);
    const int c3 = cell_of(b.w) * GRID + cell_of(b.z);

    atomicAdd(&hist[c0], 1u);
    atomicAdd(&hist[c1], 1u);
    atomicAdd(&hist[c2], 1u);
    atomicAdd(&hist[c3], 1u);

    float msum = a.x + a.y + a.z + a.w + b.x + b.y + b.z + b.w;
    if (set == 1) {
        #pragma unroll
        for (int o = 16; o; o >>= 1) msum += __shfl_xor_sync(0xFFFFFFFFu, msum, o);
        if (lane == 0) mred[warp] = msum;
    }
    if (slot == 0 && tid == 0) { *out = 0.f; g_tail_count = 0; }
    __syncthreads();

    if (set == 1 && tid == 0) {
        float t = 0.f;
        #pragma unroll
        for (int w = 0; w < 32; w++) t += mred[w];
        g_mask[obj] = (t >= 0.f) ? 1.f : 0.f;
    }

    // single-pass exclusive scan over 4096 bins (4 bins/thread)
    uint4 v4 = ((uint4*)hist)[tid];
    const unsigned int tsum = v4.x + v4.y + v4.z + v4.w;

    unsigned int incl = tsum;
    #pragma unroll
    for (int o = 1; o < 32; o <<= 1) {
        unsigned int n = __shfl_up_sync(0xFFFFFFFFu, incl, o);
        if (lane >= o) incl += n;
    }
    if (lane == 31) wsum[warp] = incl;
    __syncthreads();

    if (warp == 0) {
        unsigned int w = wsum[lane];
        unsigned int wi = w;
        #pragma unroll
        for (int o = 1; o < 32; o <<= 1) {
            unsigned int n = __shfl_up_sync(0xFFFFFFFFu, wi, o);
            if (lane >= o) wi += n;
        }
        wsum[lane] = wi - w;
    }
    __syncthreads();

    const unsigned int base = (incl - tsum) + wsum[warp];
    uint4 o4;
    o4.x = base;
    o4.y = base + v4.x;
    o4.z = base + v4.x + v4.y;
    o4.w = base + v4.x + v4.y + v4.z;
    ((uint4*)hist)[tid] = o4;

    unsigned int* cs = g_cstart + (size_t)slot * CSTRIDE;
    ((uint4*)cs)[tid] = o4;
    if (tid == 0) { cs[NBINS] = P; cs[NBINS + 1] = P; cs[NBINS + 2] = P; cs[NBINS + 3] = P; }
    __syncthreads();

    // scatter into smem, then coalesced flush
    {
        unsigned int p0 = atomicAdd(&hist[c0], 1u);
        unsigned int p1 = atomicAdd(&hist[c1], 1u);
        unsigned int p2 = atomicAdd(&hist[c2], 1u);
        unsigned int p3 = atomicAdd(&hist[c3], 1u);
        s_sorted[p0] = make_float2(a.x, a.y);
        s_sorted[p1] = make_float2(a.z, a.w);
        s_sorted[p2] = make_float2(b.x, b.y);
        s_sorted[p3] = make_float2(b.z, b.w);
    }
    __syncthreads();

    float4* dst = (float4*)(g_pts + (size_t)slot * P);
    const float4* ssrc = (const float4*)s_sorted;
    dst[tid]        = ssrc[tid];
    dst[tid + TB]   = ssrc[tid + TB];
}

// ---------------------------------------------------------------------------
// Kernel 2 (phase 1): 3x3 NN + 5x5 escalation, windowed smem staging.
// Chunk queries are sorted row-major -> rows span [r0, r1]; all cells either
// phase touches lie in rows [r0-2, r1+2]. Stage ONLY that contiguous window
// of points and cell starts. Exact-stop bounds unchanged.
// ---------------------------------------------------------------------------
__global__ void __launch_bounds__(256)
query_kernel(float* __restrict__ out)
{
    const int b     = blockIdx.x;
    const int chunk = b & 15;
    const int obj   = (b >> 4) & 15;
    const int dir   = b >> 8;

    const int qslot = (dir == 0) ? obj      : 16 + obj;
    const int tslot = (dir == 0) ? 16 + obj : obj;

    __shared__ __align__(16) float2       s_pts[P];           // 32 KB (worst case)
    __shared__ __align__(16) unsigned int s_cs[NBINS + 1];    // 16.4 KB (worst case)
    __shared__ int s_jlo, s_klo, s_khi, s_ncs;

    const unsigned int* __restrict__ cs = g_cstart + (size_t)tslot * CSTRIDE;

    if (threadIdx.x == 0) {
        const float2 qf = g_pts[(size_t)qslot * P + chunk * 256];
        const float2 ql = g_pts[(size_t)qslot * P + chunk * 256 + 255];
        const int r0 = cell_of(qf.y), r1 = cell_of(ql.y);   // sorted -> r0 <= r1
        const int jlo = max(r0 - 2, 0), jhi = min(r1 + 2, GRID - 1);
        s_jlo = jlo;
        s_klo = (int)cs[jlo * GRID];
        s_khi = (jhi == GRID - 1) ? P : (int)cs[(jhi + 1) * GRID];
        s_ncs = (jhi - jlo + 1) * GRID + 1;
    }
    __syncthreads();

    const int jlo  = s_jlo;
    const int klo  = s_klo;
    const int cbase = jlo * GRID;
    {
        const int npts = s_khi - klo;
        const float2* src = g_pts + (size_t)tslot * P + klo;
        for (int i = threadIdx.x; i < npts; i += 256) s_pts[i] = src[i];
        const int ncs = s_ncs;
        for (int i = threadIdx.x; i < ncs; i += 256) s_cs[i] = cs[cbase + i];
    }
    __syncthreads();

    const int qi  = chunk * 256 + threadIdx.x;
    const int qid = (dir * NOBJ + obj) * P + qi;
    const float2 qp = g_pts[(size_t)qslot * P + qi];
    const float qx = qp.x, qy = qp.y;
    const int cx = cell_of(qx), cy = cell_of(qy);

    float best = FLT_MAX;
    {
        const int j0 = max(cy - 1, 0), j1 = min(cy + 1, GRID - 1);
        const int i0 = max(cx - 1, 0), i1 = min(cx + 1, GRID - 1);
        for (int j = j0; j <= j1; j++) {
            const int k0 = (int)s_cs[j * GRID + i0 - cbase] - klo;
            const int k1 = (int)s_cs[j * GRID + i1 + 1 - cbase] - klo;
            for (int k = k0; k < k1; k++) {
                const float2 p = s_pts[k];
                const float dx = qx - p.x;
                const float dy = qy - p.y;
                best = fminf(best, fmaf(dx, dx, dy * dy));
            }
        }
    }

    // escalate to the 5x5 border ring if 3x3 did not prove the NN
    if (best > CELL2) {
        const int j0 = max(cy - 2, 0), j1 = min(cy + 2, GRID - 1);
        const int i0 = max(cx - 2, 0), i1 = min(cx + 2, GRID - 1);
        for (int j = j0; j <= j1; j++) {
            const bool edge_row = (j == cy - 2) || (j == cy + 2);
            if (!edge_row) {
                if (cx - 2 >= 0) {
                    const int c = j * GRID + (cx - 2) - cbase;
                    const int k0 = (int)s_cs[c] - klo, k1 = (int)s_cs[c + 1] - klo;
                    for (int k = k0; k < k1; k++) {
                        const float2 p = s_pts[k];
                        const float dx = qx - p.x;
                        const float dy = qy - p.y;
                        best = fminf(best, fmaf(dx, dx, dy * dy));
                    }
                }
                if (cx + 2 <= GRID - 1) {
                    const int c = j * GRID + (cx + 2) - cbase;
                    const int k0 = (int)s_cs[c] - klo, k1 = (int)s_cs[c + 1] - klo;
                    for (int k = k0; k < k1; k++) {
                        const float2 p = s_pts[k];
                        const float dx = qx - p.x;
                        const float dy = qy - p.y;
                        best = fminf(best, fmaf(dx, dx, dy * dy));
                    }
                }
                continue;
            }
            const int k0 = (int)s_cs[j * GRID + i0 - cbase] - klo;
            const int k1 = (int)s_cs[j * GRID + i1 + 1 - cbase] - klo;
            for (int k = k0; k < k1; k++) {
                const float2 p = s_pts[k];
                const float dx = qx - p.x;
                const float dy = qy - p.y;
                best = fminf(best, fmaf(dx, dx, dy * dy));
            }
        }
    }

    const bool fail = (best > CELL2_2);
    float acc = fail ? 0.f : sqrtf(fmaxf(best, EPSF)) * g_mask[obj];

    // warp-aggregated tail push
    const unsigned int m = __ballot_sync(0xFFFFFFFFu, fail);
    if (m) {
        const int lane = threadIdx.x & 31;
        const int leader = __ffs(m) - 1;
        unsigned int tbase = 0;
        if (lane == leader) tbase = atomicAdd(&g_tail_count, (unsigned)__popc(m));
        tbase = __shfl_sync(0xFFFFFFFFu, tbase, leader);
        if (fail) {
            const int off = tbase + __popc(m & ((1u << lane) - 1u));
            g_tail_qid[off]  = qid;
            g_tail_best[off] = best;
        }
    }

    // block reduce + atomic
    #pragma unroll
    for (int o = 16; o; o >>= 1) acc += __shfl_xor_sync(0xFFFFFFFFu, acc, o);
    __shared__ float red[8];
    if ((threadIdx.x & 31) == 0) red[threadIdx.x >> 5] = acc;
    __syncthreads();
    if (threadIdx.x == 0) {
        float tot = 0.f;
        #pragma unroll
        for (int w = 0; w < 8; w++) tot += red[w];
        if (tot != 0.f)
            atomicAdd(out, tot * (0.5f / ((float)NOBJ * (float)P)));
    }
}

// ---------------------------------------------------------------------------
// Kernel 3 (phase 2): residual tail queries, one WARP per query.
// Box radius doubles 4,8,...,64; exact stop best <= (r*CELL)^2.
// ---------------------------------------------------------------------------
__global__ void __launch_bounds__(128)
tail_kernel(float* __restrict__ out)
{
    const int warps_per_cta = 128 / 32;
    const int gwarp = blockIdx.x * warps_per_cta + (threadIdx.x >> 5);
    const int nwarp = gridDim.x * warps_per_cta;
    const int lane  = threadIdx.x & 31;

    const unsigned int count = g_tail_count;
    float acc = 0.f;

    for (unsigned int t = gwarp; t < count; t += nwarp) {
        const int qid = g_tail_qid[t];
        float best    = g_tail_best[t];
        const int dir = qid >> 16;
        const int obj = (qid >> 12) & 15;
        const int qi  = qid & (P - 1);

        const int qslot = (dir == 0) ? obj      : 16 + obj;
        const int tslot = (dir == 0) ? 16 + obj : obj;

        const float2 qp = g_pts[(size_t)qslot * P + qi];
        const float qx = qp.x, qy = qp.y;
        const unsigned int* __restrict__ cs = g_cstart + (size_t)tslot * CSTRIDE;
        const float2* __restrict__ tp = g_pts + (size_t)tslot * P;

        const int cx = cell_of(qx), cy = cell_of(qy);

        for (int r = 4; r <= GRID; r <<= 1) {
            const int y0 = max(cy - r, 0), y1 = min(cy + r, GRID - 1);
            const int x0 = max(cx - r, 0), x1 = min(cx + r, GRID - 1);

            float lb = FLT_MAX;
            for (int j = y0 + lane; j <= y1; j += 32) {
                const unsigned int k0 = __ldg(&cs[j * GRID + x0]);
                const unsigned int k1 = __ldg(&cs[j * GRID + x1 + 1]);
                for (unsigned int k = k0; k < k1; k++) {
                    const float2 p = __ldg(&tp[k]);
                    const float dx = qx - p.x;
                    const float dy = qy - p.y;
                    lb = fminf(lb, fmaf(dx, dx, dy * dy));
                }
            }
            #pragma unroll
            for (int o = 16; o; o >>= 1)
                lb = fminf(lb, __shfl_xor_sync(0xFFFFFFFFu, lb, o));
            best = fminf(best, lb);

            const bool full = (x0 == 0) && (y0 == 0) && (x1 == GRID - 1) && (y1 == GRID - 1);
            const float rb = (float)r * CELLF;
            if (best <= rb * rb || full) break;
        }

        acc += sqrtf(fmaxf(best, EPSF)) * g_mask[obj];   // identical on all lanes
    }

    if (lane == 0 && acc != 0.f)
        atomicAdd(out, acc * (0.5f / ((float)NOBJ * (float)P)));
}

// ---------------------------------------------------------------------------
extern "C" void kernel_launch(void* const* d_in, const int* in_sizes, int n_in,
                              void* d_out, int out_size)
{
    const float* set1 = (const float*)d_in[0];
    const float* set2 = (const float*)d_in[1];
    float* out = (float*)d_out;

    build_kernel<<<NSLOT, TB>>>(set1, set2, out);
    query_kernel<<<512, 256>>>(out);
    tail_kernel<<<148, 128>>>(out);
}